// round 13
// baseline (speedup 1.0000x reference)
#include <cuda_runtime.h>
#include <cstdint>

// Round 11: packed-fragment tf32 HMMA GEMMs, 64x32 warp tiles (2Mx4N warps).
//   prep: round W1/W2/x to tf32 and repack into mma.m16n8k8 fragment order.
//   K1: Htf = packedB( silu(W1 @ X + b1) )    CTA 128(f) x 128(l), K=256
//   K2: y   = W2 @ Ht + b2                    CTA 128(c) x 128(l), K=1024
// Per k0-step per warp: 4 LDS.128 + 4 LDS.64 -> 32 HMMA (MMA:LDS = 4.0,
// halving smem fragment traffic per MMA vs round 6 -- L1 was co-limiting at 51%).
//
// Packed layouts (per K-chunk kc of 32, g=lane>>2, tg=lane&3):
//   A[k0][m8][lane][4] : (A[m8*16+g][k0*8+tg], A[..+8+g][tg], A[g][tg+4], A[+8+g][tg+4])
//   B[k0][nb][lane][2] : (B[nb*8+g][k0*8+tg], B[nb*8+g][k0*8+tg+4])      (B[n][k])

namespace {

constexpr int E_ = 16, C_ = 256, F_ = 1024, L_ = 1024, B_ = 8;
constexpr int CHUNK = 4096;  // floats per packed 32-K chunk (16 KB)

__device__ float g_W1f[(size_t)E_ * F_ * C_];        //   16 MB
__device__ float g_W2f[(size_t)E_ * C_ * F_];        //   16 MB
__device__ float g_Xf [(size_t)B_ * E_ * C_ * L_];   //  128 MB
__device__ float g_Htf[(size_t)B_ * E_ * L_ * F_];   //  512 MB

__device__ __forceinline__ unsigned tf32b(float v) {
    unsigned r; asm("cvt.rna.tf32.f32 %0, %1;" : "=r"(r) : "f"(v)); return r;
}
__device__ __forceinline__ float f2tf32(float v) { return __uint_as_float(tf32b(v)); }

__device__ __forceinline__ void mma_tf32(float* d, const unsigned* a,
                                         unsigned b0, unsigned b1) {
    asm volatile(
        "mma.sync.aligned.m16n8k8.row.col.f32.tf32.tf32.f32 "
        "{%0,%1,%2,%3}, {%4,%5,%6,%7}, {%8,%9}, {%0,%1,%2,%3};\n"
        : "+f"(d[0]), "+f"(d[1]), "+f"(d[2]), "+f"(d[3])
        : "r"(a[0]), "r"(a[1]), "r"(a[2]), "r"(a[3]), "r"(b0), "r"(b1));
}
__device__ __forceinline__ uint32_t smem_u32(const void* p) {
    uint32_t a;
    asm("{ .reg .u64 t; cvta.to.shared.u64 t, %1; cvt.u32.u64 %0, t; }" : "=r"(a) : "l"(p));
    return a;
}
__device__ __forceinline__ void cp16(uint32_t dst, const void* src) {
    asm volatile("cp.async.cg.shared.global [%0], [%1], 16;\n" :: "r"(dst), "l"(src));
}
__device__ __forceinline__ void cp_commit() { asm volatile("cp.async.commit_group;\n"); }
template <int N> __device__ __forceinline__ void cp_wait() {
    asm volatile("cp.async.wait_group %0;\n" :: "n"(N));
}

constexpr size_t MAIN_SMEM = (size_t)(3 * 2 * CHUNK) * 4;  // 98304 B (3 stages x A+B)
constexpr int ST1_STR = 132;  // K1 staging [l][f]
constexpr int ST2_STR = 136;  // K2 staging [c][l]

}  // namespace

// ===================== prep kernels =====================
// W1 -> g_W1f[e][ft(8)][kc(8)][CHUNK]; A-matrix rows f (128/tile), k = c
__global__ __launch_bounds__(256, 4)
void prep_w1(const float* __restrict__ W1) {
    __shared__ float ws[128][36];
    const int e = blockIdx.y, ft = blockIdx.x, tid = threadIdx.x;
    const float* src = W1 + (size_t)(e * F_ + ft * 128) * C_;
    float* dst = g_W1f + ((size_t)(e * 8 + ft) * 8) * CHUNK;
    for (int kc = 0; kc < 8; kc++) {
        __syncthreads();
        #pragma unroll
        for (int it = 0; it < 4; it++) {  // 128 rows x 8 float4
            const int idx = tid + it * 256, f = idx >> 3, c4 = (idx & 7) * 4;
            const float4 v = *(const float4*)(src + (size_t)f * C_ + kc * 32 + c4);
            ws[f][c4] = f2tf32(v.x); ws[f][c4 + 1] = f2tf32(v.y);
            ws[f][c4 + 2] = f2tf32(v.z); ws[f][c4 + 3] = f2tf32(v.w);
        }
        __syncthreads();
        #pragma unroll
        for (int it = 0; it < 4; it++) {  // 1024 float4 packed
            const int i4 = tid + it * 256;
            const int k0 = i4 >> 8, m8 = (i4 >> 5) & 7, lane = i4 & 31;
            const int g = lane >> 2, tg = lane & 3;
            float4 v;
            v.x = ws[m8 * 16 + g][k0 * 8 + tg];
            v.y = ws[m8 * 16 + 8 + g][k0 * 8 + tg];
            v.z = ws[m8 * 16 + g][k0 * 8 + tg + 4];
            v.w = ws[m8 * 16 + 8 + g][k0 * 8 + tg + 4];
            *(float4*)(dst + (size_t)kc * CHUNK + i4 * 4) = v;
        }
    }
}

// W2 -> g_W2f[e][cb(2)][kc(32)][CHUNK]; A-matrix rows c (128/tile), k = f
__global__ __launch_bounds__(256, 4)
void prep_w2(const float* __restrict__ W2) {
    __shared__ float ws[128][36];
    const int e = blockIdx.y, cb = blockIdx.x, tid = threadIdx.x;
    const float* src = W2 + (size_t)(e * C_ + cb * 128) * F_;
    float* dst = g_W2f + ((size_t)(e * 2 + cb) * 32) * CHUNK;
    for (int kc = 0; kc < 32; kc++) {
        __syncthreads();
        #pragma unroll
        for (int it = 0; it < 4; it++) {
            const int idx = tid + it * 256, c = idx >> 3, f4 = (idx & 7) * 4;
            const float4 v = *(const float4*)(src + (size_t)c * F_ + kc * 32 + f4);
            ws[c][f4] = f2tf32(v.x); ws[c][f4 + 1] = f2tf32(v.y);
            ws[c][f4 + 2] = f2tf32(v.z); ws[c][f4 + 3] = f2tf32(v.w);
        }
        __syncthreads();
        #pragma unroll
        for (int it = 0; it < 4; it++) {
            const int i4 = tid + it * 256;
            const int k0 = i4 >> 8, m8 = (i4 >> 5) & 7, lane = i4 & 31;
            const int g = lane >> 2, tg = lane & 3;
            float4 v;
            v.x = ws[m8 * 16 + g][k0 * 8 + tg];
            v.y = ws[m8 * 16 + 8 + g][k0 * 8 + tg];
            v.z = ws[m8 * 16 + g][k0 * 8 + tg + 4];
            v.w = ws[m8 * 16 + 8 + g][k0 * 8 + tg + 4];
            *(float4*)(dst + (size_t)kc * CHUNK + i4 * 4) = v;
        }
    }
}

// x -> g_Xf[p][lt(8)][kc(8)][CHUNK]; B-matrix n = l (128/tile), k = c
__global__ __launch_bounds__(256, 4)
void prep_x(const float* __restrict__ x) {
    __shared__ float xs[32][136];
    const int p = blockIdx.y, lt = blockIdx.x, tid = threadIdx.x;
    const float* src = x + (size_t)p * C_ * L_ + lt * 128;
    float* dst = g_Xf + ((size_t)(p * 8 + lt) * 8) * CHUNK;
    for (int kc = 0; kc < 8; kc++) {
        __syncthreads();
        #pragma unroll
        for (int it = 0; it < 4; it++) {  // 32 rows x 32 float4
            const int idx = tid + it * 256, c = idx >> 5, l4 = (idx & 31) * 4;
            const float4 v = *(const float4*)(src + (size_t)(kc * 32 + c) * L_ + l4);
            xs[c][l4] = f2tf32(v.x); xs[c][l4 + 1] = f2tf32(v.y);
            xs[c][l4 + 2] = f2tf32(v.z); xs[c][l4 + 3] = f2tf32(v.w);
        }
        __syncthreads();
        #pragma unroll
        for (int it = 0; it < 8; it++) {  // 2048 float2 packed
            const int i2 = tid + it * 256;
            const int k0 = i2 >> 9, nb = (i2 >> 5) & 15, lane = i2 & 31;
            const int g = lane >> 2, tg = lane & 3;
            float2 v;
            v.x = xs[k0 * 8 + tg][nb * 8 + g];
            v.y = xs[k0 * 8 + tg + 4][nb * 8 + g];
            *(float2*)(dst + (size_t)kc * CHUNK + i2 * 2) = v;
        }
    }
}

// ===================== K1: Htf = packedB(silu(W1 @ X + b1)) =====================
__global__ __launch_bounds__(256, 2)
void experts_k1(const float* __restrict__ b1) {
    extern __shared__ float sm[];
    const uint32_t sm_u = smem_u32(sm);

    const int tid = threadIdx.x, warp = tid >> 5, lane = tid & 31;
    const int g = lane >> 2, tg = lane & 3;
    const int p = blockIdx.z, e = p & (E_ - 1);
    const int ft = blockIdx.y, lt = blockIdx.x;

    const float* Aglob = g_W1f + ((size_t)(e * 8 + ft) * 8) * CHUNK;
    const float* Bglob = g_Xf + ((size_t)(p * 8 + lt) * 8) * CHUNK;

    const int warpM = warp >> 2, warpN = warp & 3;  // 2x4: warp tile 64(f) x 32(l)

    auto load_chunk = [&](int kc, int buf) {
        const uint32_t ad = sm_u + (uint32_t)(buf * 2 * CHUNK) * 4;
        const float* as = Aglob + (size_t)kc * CHUNK;
        const float* bs = Bglob + (size_t)kc * CHUNK;
        #pragma unroll
        for (int it = 0; it < 4; it++) {
            const int i4 = tid + it * 256;
            cp16(ad + (uint32_t)i4 * 16, as + i4 * 4);
            cp16(ad + (uint32_t)(CHUNK + i4 * 4) * 4, bs + i4 * 4);
        }
    };

    float acc[4][4][4];
    #pragma unroll
    for (int mi = 0; mi < 4; mi++)
        #pragma unroll
        for (int ni = 0; ni < 4; ni++)
            #pragma unroll
            for (int r = 0; r < 4; r++) acc[mi][ni][r] = 0.f;

    load_chunk(0, 0); cp_commit();
    load_chunk(1, 1); cp_commit();

    for (int kc = 0; kc < 8; kc++) {
        cp_wait<1>();
        __syncthreads();
        if (kc + 2 < 8) load_chunk(kc + 2, (kc + 2) % 3);
        cp_commit();

        const float* Ab = sm + (kc % 3) * 2 * CHUNK;
        const float* Bb = Ab + CHUNK;
        #pragma unroll
        for (int k0 = 0; k0 < 4; k0++) {
            unsigned a[4][4];
            #pragma unroll
            for (int mi = 0; mi < 4; mi++) {
                const int m8 = warpM * 4 + mi;
                const float4 v = *(const float4*)(Ab + ((k0 * 8 + m8) * 32 + lane) * 4);
                a[mi][0] = __float_as_uint(v.x); a[mi][1] = __float_as_uint(v.y);
                a[mi][2] = __float_as_uint(v.z); a[mi][3] = __float_as_uint(v.w);
            }
            unsigned bf[4][2];
            #pragma unroll
            for (int ni = 0; ni < 4; ni++) {
                const int nb = warpN * 4 + ni;
                const float2 b = *(const float2*)(Bb + ((k0 * 16 + nb) * 32 + lane) * 2);
                bf[ni][0] = __float_as_uint(b.x); bf[ni][1] = __float_as_uint(b.y);
            }
            #pragma unroll
            for (int ni = 0; ni < 4; ni++)
                #pragma unroll
                for (int mi = 0; mi < 4; mi++)
                    mma_tf32(acc[mi][ni], a[mi], bf[ni][0], bf[ni][1]);
        }
    }
    cp_wait<0>();
    __syncthreads();  // pipeline buffers free -> staging

    float bias[4][2];
    #pragma unroll
    for (int mi = 0; mi < 4; mi++)
        #pragma unroll
        for (int hi = 0; hi < 2; hi++)
            bias[mi][hi] = __ldg(b1 + e * F_ + ft * 128 + (warpM * 4 + mi) * 16 + g + hi * 8);

    float* stg = sm;  // [l=128][ST1_STR]  (67.6 KB)
    #pragma unroll
    for (int mi = 0; mi < 4; mi++)
        #pragma unroll
        for (int ni = 0; ni < 4; ni++)
            #pragma unroll
            for (int r = 0; r < 4; r++) {
                const int fL = (warpM * 4 + mi) * 16 + g + (r >> 1) * 8;
                const int l = warpN * 32 + ni * 8 + tg * 2 + (r & 1);
                float v = acc[mi][ni][r] + bias[mi][r >> 1];
                v = v / (1.f + __expf(-v));  // silu
                stg[l * ST1_STR + fL] = f2tf32(v);
            }
    __syncthreads();

    // write Ht in K2's packed-B layout: [p][lt][kc(32)][k0][nb][lane][2]
    float* dst = g_Htf + (((size_t)(p * 8 + lt) * 32 + ft * 4)) * CHUNK;
    #pragma unroll
    for (int it = 0; it < 32; it++) {
        const int i2 = tid + it * 256;             // [0, 8192)
        const int kcL = i2 >> 11, rem = i2 & 2047;
        const int k0 = rem >> 9, nb = (rem >> 5) & 15, ln = rem & 31;
        const int gg = ln >> 2, tt = ln & 3;
        const int l = nb * 8 + gg;
        const int fL = kcL * 32 + k0 * 8 + tt;
        float2 v;
        v.x = stg[l * ST1_STR + fL];
        v.y = stg[l * ST1_STR + fL + 4];
        *(float2*)(dst + (size_t)kcL * CHUNK + rem * 2) = v;
    }
}

// ===================== K2: y = W2 @ Ht + b2 =====================
__global__ __launch_bounds__(256, 2)
void experts_k2(const float* __restrict__ b2, float* __restrict__ y) {
    extern __shared__ float sm[];
    const uint32_t sm_u = smem_u32(sm);

    const int tid = threadIdx.x, warp = tid >> 5, lane = tid & 31;
    const int g = lane >> 2, tg = lane & 3;
    const int p = blockIdx.z, e = p & (E_ - 1);
    const int cb = blockIdx.y, lt = blockIdx.x;

    const float* Aglob = g_W2f + ((size_t)(e * 2 + cb) * 32) * CHUNK;
    const float* Bglob = g_Htf + ((size_t)(p * 8 + lt) * 32) * CHUNK;

    const int warpM = warp >> 2, warpN = warp & 3;  // 2x4: warp tile 64(c) x 32(l)

    auto load_chunk = [&](int kc, int buf) {
        const uint32_t ad = sm_u + (uint32_t)(buf * 2 * CHUNK) * 4;
        const float* as = Aglob + (size_t)kc * CHUNK;
        const float* bs = Bglob + (size_t)kc * CHUNK;
        #pragma unroll
        for (int it = 0; it < 4; it++) {
            const int i4 = tid + it * 256;
            cp16(ad + (uint32_t)i4 * 16, as + i4 * 4);
            cp16(ad + (uint32_t)(CHUNK + i4 * 4) * 4, bs + i4 * 4);
        }
    };

    float acc[4][4][4];
    #pragma unroll
    for (int mi = 0; mi < 4; mi++)
        #pragma unroll
        for (int ni = 0; ni < 4; ni++)
            #pragma unroll
            for (int r = 0; r < 4; r++) acc[mi][ni][r] = 0.f;

    load_chunk(0, 0); cp_commit();
    load_chunk(1, 1); cp_commit();

    for (int kc = 0; kc < 32; kc++) {
        cp_wait<1>();
        __syncthreads();
        if (kc + 2 < 32) load_chunk(kc + 2, (kc + 2) % 3);
        cp_commit();

        const float* Ab = sm + (kc % 3) * 2 * CHUNK;
        const float* Bb = Ab + CHUNK;
        #pragma unroll
        for (int k0 = 0; k0 < 4; k0++) {
            unsigned a[4][4];
            #pragma unroll
            for (int mi = 0; mi < 4; mi++) {
                const int m8 = warpM * 4 + mi;
                const float4 v = *(const float4*)(Ab + ((k0 * 8 + m8) * 32 + lane) * 4);
                a[mi][0] = __float_as_uint(v.x); a[mi][1] = __float_as_uint(v.y);
                a[mi][2] = __float_as_uint(v.z); a[mi][3] = __float_as_uint(v.w);
            }
            unsigned bf[4][2];
            #pragma unroll
            for (int ni = 0; ni < 4; ni++) {
                const int nb = warpN * 4 + ni;
                const float2 b = *(const float2*)(Bb + ((k0 * 16 + nb) * 32 + lane) * 2);
                bf[ni][0] = __float_as_uint(b.x); bf[ni][1] = __float_as_uint(b.y);
            }
            #pragma unroll
            for (int ni = 0; ni < 4; ni++)
                #pragma unroll
                for (int mi = 0; mi < 4; mi++)
                    mma_tf32(acc[mi][ni], a[mi], bf[ni][0], bf[ni][1]);
        }
    }
    cp_wait<0>();
    __syncthreads();  // pipeline buffers free -> staging

    float bias[4][2];
    #pragma unroll
    for (int mi = 0; mi < 4; mi++)
        #pragma unroll
        for (int hi = 0; hi < 2; hi++)
            bias[mi][hi] = __ldg(b2 + e * C_ + cb * 128 + (warpM * 4 + mi) * 16 + g + hi * 8);

    float* stg = sm;  // [c=128][ST2_STR]  (69.6 KB)
    #pragma unroll
    for (int mi = 0; mi < 4; mi++)
        #pragma unroll
        for (int ni = 0; ni < 4; ni++)
            #pragma unroll
            for (int r2 = 0; r2 < 2; r2++) {
                const int c = (warpM * 4 + mi) * 16 + g + r2 * 8;
                const int l = warpN * 32 + ni * 8 + tg * 2;
                float2 v;
                v.x = acc[mi][ni][r2 * 2 + 0] + bias[mi][r2];
                v.y = acc[mi][ni][r2 * 2 + 1] + bias[mi][r2];
                *(float2*)(stg + c * ST2_STR + l) = v;
            }
    __syncthreads();

    float* yp = y + ((size_t)p * C_ + cb * 128) * L_ + lt * 128;
    #pragma unroll
    for (int it = 0; it < 16; it++) {
        const int i4 = tid + it * 256;
        const int c = i4 >> 5, lo = (i4 & 31) * 4;
        const float4 v = *(const float4*)(stg + c * ST2_STR + lo);
        *(float4*)(yp + (size_t)c * L_ + lo) = v;
    }
}

extern "C" void kernel_launch(void* const* d_in, const int* in_sizes, int n_in,
                              void* d_out, int out_size) {
    const float* x  = (const float*)d_in[0];
    const float* W1 = (const float*)d_in[1];
    const float* b1 = (const float*)d_in[2];
    const float* W2 = (const float*)d_in[3];
    const float* b2 = (const float*)d_in[4];
    float* y = (float*)d_out;

    cudaFuncSetAttribute(experts_k1, cudaFuncAttributeMaxDynamicSharedMemorySize, (int)MAIN_SMEM);
    cudaFuncSetAttribute(experts_k2, cudaFuncAttributeMaxDynamicSharedMemorySize, (int)MAIN_SMEM);

    prep_x <<<dim3(8, B_ * E_), 256>>>(x);     // 1024 CTAs
    prep_w1<<<dim3(8, E_), 256>>>(W1);         //  128 CTAs
    prep_w2<<<dim3(2, E_), 256>>>(W2);         //   32 CTAs

    experts_k1<<<dim3(8, 8, B_ * E_), 256, MAIN_SMEM>>>(b1);        // 8192 CTAs
    experts_k2<<<dim3(8, 2, B_ * E_), 256, MAIN_SMEM>>>(b2, y);     // 2048 CTAs
}

// round 14
// speedup vs baseline: 1.0627x; 1.0627x over previous
#include <cuda_runtime.h>
#include <cstdint>

// Round 13: packed-fragment tf32 HMMA, CTA 128(m)x64(n), warp tile 32x32,
// 3 CTAs/SM (24 warps, occ 37.5%) -- occupancy/latency experiment.
//   prep: round W1/W2/x to tf32, repack into mma.m16n8k8 fragment order (unchanged).
//   K1: Htf = packedB( silu(W1 @ X + b1) )    CTA 128(f) x 64(l), K=256
//   K2: y   = W2 @ Ht + b2                    CTA 128(c) x 64(l), K=1024
// 3-stage cp.async ring (24KB/stage), 1 barrier per K-chunk.
//
// Packed layouts (per K-chunk kc of 32, g=lane>>2, tg=lane&3):
//   A[k0][m8][lane][4] : (A[m8*16+g][k0*8+tg], A[..+8+g][tg], A[g][tg+4], A[+8+g][tg+4])
//   B[k0][nb][lane][2] : (B[nb*8+g][k0*8+tg], B[nb*8+g][k0*8+tg+4])      (B[n][k])
// A CTA consumes the full A chunk (m=128) and the nb-half of the B chunk (n=64).

namespace {

constexpr int E_ = 16, C_ = 256, F_ = 1024, L_ = 1024, B_ = 8;
constexpr int CHUNK = 4096;   // floats per packed 32-K x 128-row chunk (16 KB)
constexpr int BHALF = 2048;   // floats per 32-K x 64-col B half-chunk (8 KB)

__device__ float g_W1f[(size_t)E_ * F_ * C_];        //   16 MB
__device__ float g_W2f[(size_t)E_ * C_ * F_];        //   16 MB
__device__ float g_Xf [(size_t)B_ * E_ * C_ * L_];   //  128 MB
__device__ float g_Htf[(size_t)B_ * E_ * L_ * F_];   //  512 MB

__device__ __forceinline__ unsigned tf32b(float v) {
    unsigned r; asm("cvt.rna.tf32.f32 %0, %1;" : "=r"(r) : "f"(v)); return r;
}
__device__ __forceinline__ float f2tf32(float v) { return __uint_as_float(tf32b(v)); }

__device__ __forceinline__ void mma_tf32(float* d, const unsigned* a,
                                         unsigned b0, unsigned b1) {
    asm volatile(
        "mma.sync.aligned.m16n8k8.row.col.f32.tf32.tf32.f32 "
        "{%0,%1,%2,%3}, {%4,%5,%6,%7}, {%8,%9}, {%0,%1,%2,%3};\n"
        : "+f"(d[0]), "+f"(d[1]), "+f"(d[2]), "+f"(d[3])
        : "r"(a[0]), "r"(a[1]), "r"(a[2]), "r"(a[3]), "r"(b0), "r"(b1));
}
__device__ __forceinline__ uint32_t smem_u32(const void* p) {
    uint32_t a;
    asm("{ .reg .u64 t; cvta.to.shared.u64 t, %1; cvt.u32.u64 %0, t; }" : "=r"(a) : "l"(p));
    return a;
}
__device__ __forceinline__ void cp16(uint32_t dst, const void* src) {
    asm volatile("cp.async.cg.shared.global [%0], [%1], 16;\n" :: "r"(dst), "l"(src));
}
__device__ __forceinline__ void cp_commit() { asm volatile("cp.async.commit_group;\n"); }
template <int N> __device__ __forceinline__ void cp_wait() {
    asm volatile("cp.async.wait_group %0;\n" :: "n"(N));
}

constexpr int STAGE_FLOATS = CHUNK + BHALF;                   // 6144 (A 16KB + B 8KB)
constexpr size_t MAIN_SMEM = (size_t)(3 * STAGE_FLOATS) * 4;  // 73728 B -> 3 CTAs/SM
constexpr int ST1_STR = 132;  // K1 staging [l=64][f=128]  (33.8 KB)
constexpr int ST2_STR = 68;   // K2 staging [c=128][l=64]  (34.8 KB)

}  // namespace

// ===================== prep kernels (unchanged layouts) =====================
__global__ __launch_bounds__(256, 4)
void prep_w1(const float* __restrict__ W1) {
    __shared__ float ws[128][36];
    const int e = blockIdx.y, ft = blockIdx.x, tid = threadIdx.x;
    const float* src = W1 + (size_t)(e * F_ + ft * 128) * C_;
    float* dst = g_W1f + ((size_t)(e * 8 + ft) * 8) * CHUNK;
    for (int kc = 0; kc < 8; kc++) {
        __syncthreads();
        #pragma unroll
        for (int it = 0; it < 4; it++) {
            const int idx = tid + it * 256, f = idx >> 3, c4 = (idx & 7) * 4;
            const float4 v = *(const float4*)(src + (size_t)f * C_ + kc * 32 + c4);
            ws[f][c4] = f2tf32(v.x); ws[f][c4 + 1] = f2tf32(v.y);
            ws[f][c4 + 2] = f2tf32(v.z); ws[f][c4 + 3] = f2tf32(v.w);
        }
        __syncthreads();
        #pragma unroll
        for (int it = 0; it < 4; it++) {
            const int i4 = tid + it * 256;
            const int k0 = i4 >> 8, m8 = (i4 >> 5) & 7, lane = i4 & 31;
            const int g = lane >> 2, tg = lane & 3;
            float4 v;
            v.x = ws[m8 * 16 + g][k0 * 8 + tg];
            v.y = ws[m8 * 16 + 8 + g][k0 * 8 + tg];
            v.z = ws[m8 * 16 + g][k0 * 8 + tg + 4];
            v.w = ws[m8 * 16 + 8 + g][k0 * 8 + tg + 4];
            *(float4*)(dst + (size_t)kc * CHUNK + i4 * 4) = v;
        }
    }
}

__global__ __launch_bounds__(256, 4)
void prep_w2(const float* __restrict__ W2) {
    __shared__ float ws[128][36];
    const int e = blockIdx.y, cb = blockIdx.x, tid = threadIdx.x;
    const float* src = W2 + (size_t)(e * C_ + cb * 128) * F_;
    float* dst = g_W2f + ((size_t)(e * 2 + cb) * 32) * CHUNK;
    for (int kc = 0; kc < 32; kc++) {
        __syncthreads();
        #pragma unroll
        for (int it = 0; it < 4; it++) {
            const int idx = tid + it * 256, c = idx >> 3, f4 = (idx & 7) * 4;
            const float4 v = *(const float4*)(src + (size_t)c * F_ + kc * 32 + f4);
            ws[c][f4] = f2tf32(v.x); ws[c][f4 + 1] = f2tf32(v.y);
            ws[c][f4 + 2] = f2tf32(v.z); ws[c][f4 + 3] = f2tf32(v.w);
        }
        __syncthreads();
        #pragma unroll
        for (int it = 0; it < 4; it++) {
            const int i4 = tid + it * 256;
            const int k0 = i4 >> 8, m8 = (i4 >> 5) & 7, lane = i4 & 31;
            const int g = lane >> 2, tg = lane & 3;
            float4 v;
            v.x = ws[m8 * 16 + g][k0 * 8 + tg];
            v.y = ws[m8 * 16 + 8 + g][k0 * 8 + tg];
            v.z = ws[m8 * 16 + g][k0 * 8 + tg + 4];
            v.w = ws[m8 * 16 + 8 + g][k0 * 8 + tg + 4];
            *(float4*)(dst + (size_t)kc * CHUNK + i4 * 4) = v;
        }
    }
}

__global__ __launch_bounds__(256, 4)
void prep_x(const float* __restrict__ x) {
    __shared__ float xs[32][136];
    const int p = blockIdx.y, lt = blockIdx.x, tid = threadIdx.x;
    const float* src = x + (size_t)p * C_ * L_ + lt * 128;
    float* dst = g_Xf + ((size_t)(p * 8 + lt) * 8) * CHUNK;
    for (int kc = 0; kc < 8; kc++) {
        __syncthreads();
        #pragma unroll
        for (int it = 0; it < 4; it++) {
            const int idx = tid + it * 256, c = idx >> 5, l4 = (idx & 31) * 4;
            const float4 v = *(const float4*)(src + (size_t)(kc * 32 + c) * L_ + l4);
            xs[c][l4] = f2tf32(v.x); xs[c][l4 + 1] = f2tf32(v.y);
            xs[c][l4 + 2] = f2tf32(v.z); xs[c][l4 + 3] = f2tf32(v.w);
        }
        __syncthreads();
        #pragma unroll
        for (int it = 0; it < 8; it++) {
            const int i2 = tid + it * 256;
            const int k0 = i2 >> 9, nb = (i2 >> 5) & 15, lane = i2 & 31;
            const int g = lane >> 2, tg = lane & 3;
            float2 v;
            v.x = xs[k0 * 8 + tg][nb * 8 + g];
            v.y = xs[k0 * 8 + tg + 4][nb * 8 + g];
            *(float2*)(dst + (size_t)kc * CHUNK + i2 * 2) = v;
        }
    }
}

// ===================== K1: Htf = packedB(silu(W1 @ X + b1)) =====================
__global__ __launch_bounds__(256, 3)
void experts_k1(const float* __restrict__ b1) {
    extern __shared__ float sm[];
    const uint32_t sm_u = smem_u32(sm);

    const int tid = threadIdx.x, warp = tid >> 5, lane = tid & 31;
    const int g = lane >> 2, tg = lane & 3;
    const int p = blockIdx.z, e = p & (E_ - 1);
    const int ft = blockIdx.y, lt64 = blockIdx.x;
    const int lt = lt64 >> 1, half = lt64 & 1;

    const float* Aglob = g_W1f + ((size_t)(e * 8 + ft) * 8) * CHUNK;
    const float* Bglob = g_Xf + ((size_t)(p * 8 + lt) * 8) * CHUNK;

    const int warpM = warp >> 1, warpN = warp & 1;  // 4x2: warp tile 32(f) x 32(l)

    auto load_chunk = [&](int kc, int buf) {
        const uint32_t sd = sm_u + (uint32_t)(buf * STAGE_FLOATS) * 4;
        const float* as = Aglob + (size_t)kc * CHUNK;
        #pragma unroll
        for (int it = 0; it < 4; it++) {       // A: 16 KB
            const int i4 = tid + it * 256;
            cp16(sd + (uint32_t)i4 * 16, as + i4 * 4);
        }
        const float* bs = Bglob + (size_t)kc * CHUNK + half * 512;
        #pragma unroll
        for (int it = 0; it < 2; it++) {       // B half: 4 x 2KB regions
            const int i4 = tid + it * 256;     // [0,512)
            const int k0 = i4 >> 7, off = (i4 & 127) * 4;
            cp16(sd + (uint32_t)(CHUNK + k0 * 512 + off) * 4,
                 bs + (size_t)k0 * 1024 + off);
        }
    };

    float acc[2][4][4];
    #pragma unroll
    for (int mi = 0; mi < 2; mi++)
        #pragma unroll
        for (int ni = 0; ni < 4; ni++)
            #pragma unroll
            for (int r = 0; r < 4; r++) acc[mi][ni][r] = 0.f;

    load_chunk(0, 0); cp_commit();
    load_chunk(1, 1); cp_commit();

    for (int kc = 0; kc < 8; kc++) {
        cp_wait<1>();
        __syncthreads();
        if (kc + 2 < 8) load_chunk(kc + 2, (kc + 2) % 3);
        cp_commit();

        const float* Ab = sm + (kc % 3) * STAGE_FLOATS;
        const float* Bb = Ab + CHUNK;
        #pragma unroll
        for (int k0 = 0; k0 < 4; k0++) {
            unsigned a[2][4];
            #pragma unroll
            for (int mi = 0; mi < 2; mi++) {
                const int m8 = warpM * 2 + mi;
                const float4 v = *(const float4*)(Ab + ((k0 * 8 + m8) * 32 + lane) * 4);
                a[mi][0] = __float_as_uint(v.x); a[mi][1] = __float_as_uint(v.y);
                a[mi][2] = __float_as_uint(v.z); a[mi][3] = __float_as_uint(v.w);
            }
            unsigned bf[4][2];
            #pragma unroll
            for (int ni = 0; ni < 4; ni++) {
                const int nbl = warpN * 4 + ni;
                const float2 b = *(const float2*)(Bb + ((k0 * 8 + nbl) * 32 + lane) * 2);
                bf[ni][0] = __float_as_uint(b.x); bf[ni][1] = __float_as_uint(b.y);
            }
            #pragma unroll
            for (int ni = 0; ni < 4; ni++)
                #pragma unroll
                for (int mi = 0; mi < 2; mi++)
                    mma_tf32(acc[mi][ni], a[mi], bf[ni][0], bf[ni][1]);
        }
    }
    cp_wait<0>();
    __syncthreads();  // pipeline buffers free -> staging

    float bias[2][2];
    #pragma unroll
    for (int mi = 0; mi < 2; mi++)
        #pragma unroll
        for (int hi = 0; hi < 2; hi++)
            bias[mi][hi] = __ldg(b1 + e * F_ + ft * 128 + (warpM * 2 + mi) * 16 + g + hi * 8);

    float* stg = sm;  // [l=64][ST1_STR]
    #pragma unroll
    for (int mi = 0; mi < 2; mi++)
        #pragma unroll
        for (int ni = 0; ni < 4; ni++)
            #pragma unroll
            for (int r = 0; r < 4; r++) {
                const int fL = (warpM * 2 + mi) * 16 + g + (r >> 1) * 8;
                const int l = warpN * 32 + ni * 8 + tg * 2 + (r & 1);
                float v = acc[mi][ni][r] + bias[mi][r >> 1];
                v = v / (1.f + __expf(-v));  // silu
                stg[l * ST1_STR + fL] = f2tf32(v);
            }
    __syncthreads();

    // write Ht in K2's packed-B layout: [p][lt][kc(32)][k0][nb][lane][2]
    // this CTA covers kc in [ft*4, ft*4+4), nb in [half*8, half*8+8)
    float* dst = g_Htf + ((size_t)(p * 8 + lt) * 32 + ft * 4) * CHUNK;
    #pragma unroll
    for (int it = 0; it < 16; it++) {
        const int i2 = tid + it * 256;              // [0, 4096)
        const int kcL = i2 >> 10, rem = i2 & 1023;
        const int k0 = rem >> 8, nbl = (rem >> 5) & 7, ln = rem & 31;
        const int gg = ln >> 2, tt = ln & 3;
        const int l = nbl * 8 + gg;                 // local l in [0,64)
        const int fL = kcL * 32 + k0 * 8 + tt;      // local f in [0,128)
        float2 v;
        v.x = stg[l * ST1_STR + fL];
        v.y = stg[l * ST1_STR + fL + 4];
        const int nb = half * 8 + nbl;
        *(float2*)(dst + (size_t)kcL * CHUNK + (k0 * 16 + nb) * 64 + ln * 2) = v;
    }
}

// ===================== K2: y = W2 @ Ht + b2 =====================
__global__ __launch_bounds__(256, 3)
void experts_k2(const float* __restrict__ b2, float* __restrict__ y) {
    extern __shared__ float sm[];
    const uint32_t sm_u = smem_u32(sm);

    const int tid = threadIdx.x, warp = tid >> 5, lane = tid & 31;
    const int g = lane >> 2, tg = lane & 3;
    const int p = blockIdx.z, e = p & (E_ - 1);
    const int cb = blockIdx.y, lt64 = blockIdx.x;
    const int lt = lt64 >> 1, half = lt64 & 1;

    const float* Aglob = g_W2f + ((size_t)(e * 2 + cb) * 32) * CHUNK;
    const float* Bglob = g_Htf + ((size_t)(p * 8 + lt) * 32) * CHUNK;

    const int warpM = warp >> 1, warpN = warp & 1;  // 4x2: warp tile 32(c) x 32(l)

    auto load_chunk = [&](int kc, int buf) {
        const uint32_t sd = sm_u + (uint32_t)(buf * STAGE_FLOATS) * 4;
        const float* as = Aglob + (size_t)kc * CHUNK;
        #pragma unroll
        for (int it = 0; it < 4; it++) {
            const int i4 = tid + it * 256;
            cp16(sd + (uint32_t)i4 * 16, as + i4 * 4);
        }
        const float* bs = Bglob + (size_t)kc * CHUNK + half * 512;
        #pragma unroll
        for (int it = 0; it < 2; it++) {
            const int i4 = tid + it * 256;
            const int k0 = i4 >> 7, off = (i4 & 127) * 4;
            cp16(sd + (uint32_t)(CHUNK + k0 * 512 + off) * 4,
                 bs + (size_t)k0 * 1024 + off);
        }
    };

    float acc[2][4][4];
    #pragma unroll
    for (int mi = 0; mi < 2; mi++)
        #pragma unroll
        for (int ni = 0; ni < 4; ni++)
            #pragma unroll
            for (int r = 0; r < 4; r++) acc[mi][ni][r] = 0.f;

    load_chunk(0, 0); cp_commit();
    load_chunk(1, 1); cp_commit();

    for (int kc = 0; kc < 32; kc++) {
        cp_wait<1>();
        __syncthreads();
        if (kc + 2 < 32) load_chunk(kc + 2, (kc + 2) % 3);
        cp_commit();

        const float* Ab = sm + (kc % 3) * STAGE_FLOATS;
        const float* Bb = Ab + CHUNK;
        #pragma unroll
        for (int k0 = 0; k0 < 4; k0++) {
            unsigned a[2][4];
            #pragma unroll
            for (int mi = 0; mi < 2; mi++) {
                const int m8 = warpM * 2 + mi;
                const float4 v = *(const float4*)(Ab + ((k0 * 8 + m8) * 32 + lane) * 4);
                a[mi][0] = __float_as_uint(v.x); a[mi][1] = __float_as_uint(v.y);
                a[mi][2] = __float_as_uint(v.z); a[mi][3] = __float_as_uint(v.w);
            }
            unsigned bf[4][2];
            #pragma unroll
            for (int ni = 0; ni < 4; ni++) {
                const int nbl = warpN * 4 + ni;
                const float2 b = *(const float2*)(Bb + ((k0 * 8 + nbl) * 32 + lane) * 2);
                bf[ni][0] = __float_as_uint(b.x); bf[ni][1] = __float_as_uint(b.y);
            }
            #pragma unroll
            for (int ni = 0; ni < 4; ni++)
                #pragma unroll
                for (int mi = 0; mi < 2; mi++)
                    mma_tf32(acc[mi][ni], a[mi], bf[ni][0], bf[ni][1]);
        }
    }
    cp_wait<0>();
    __syncthreads();  // pipeline buffers free -> staging

    float bias[2][2];
    #pragma unroll
    for (int mi = 0; mi < 2; mi++)
        #pragma unroll
        for (int hi = 0; hi < 2; hi++)
            bias[mi][hi] = __ldg(b2 + e * C_ + cb * 128 + (warpM * 2 + mi) * 16 + g + hi * 8);

    float* stg = sm;  // [c=128][ST2_STR]
    #pragma unroll
    for (int mi = 0; mi < 2; mi++)
        #pragma unroll
        for (int ni = 0; ni < 4; ni++)
            #pragma unroll
            for (int r2 = 0; r2 < 2; r2++) {
                const int c = (warpM * 2 + mi) * 16 + g + r2 * 8;
                const int l = warpN * 32 + ni * 8 + tg * 2;
                float2 v;
                v.x = acc[mi][ni][r2 * 2 + 0] + bias[mi][r2];
                v.y = acc[mi][ni][r2 * 2 + 1] + bias[mi][r2];
                *(float2*)(stg + c * ST2_STR + l) = v;
            }
    __syncthreads();

    float* yp = y + ((size_t)p * C_ + cb * 128) * L_ + lt64 * 64;
    #pragma unroll
    for (int it = 0; it < 8; it++) {
        const int i4 = tid + it * 256;               // [0, 2048)
        const int c = i4 >> 4, lo = (i4 & 15) * 4;
        const float4 v = *(const float4*)(stg + c * ST2_STR + lo);
        *(float4*)(yp + (size_t)c * L_ + lo) = v;
    }
}

extern "C" void kernel_launch(void* const* d_in, const int* in_sizes, int n_in,
                              void* d_out, int out_size) {
    const float* x  = (const float*)d_in[0];
    const float* W1 = (const float*)d_in[1];
    const float* b1 = (const float*)d_in[2];
    const float* W2 = (const float*)d_in[3];
    const float* b2 = (const float*)d_in[4];
    float* y = (float*)d_out;

    cudaFuncSetAttribute(experts_k1, cudaFuncAttributeMaxDynamicSharedMemorySize, (int)MAIN_SMEM);
    cudaFuncSetAttribute(experts_k2, cudaFuncAttributeMaxDynamicSharedMemorySize, (int)MAIN_SMEM);

    prep_x <<<dim3(8, B_ * E_), 256>>>(x);     // 1024 CTAs
    prep_w1<<<dim3(8, E_), 256>>>(W1);         //  128 CTAs
    prep_w2<<<dim3(2, E_), 256>>>(W2);         //   32 CTAs

    experts_k1<<<dim3(16, 8, B_ * E_), 256, MAIN_SMEM>>>(b1);       // 16384 CTAs
    experts_k2<<<dim3(16, 2, B_ * E_), 256, MAIN_SMEM>>>(b2, y);    //  4096 CTAs
}

// round 15
// speedup vs baseline: 1.7145x; 1.6133x over previous
#include <cuda_runtime.h>
#include <cuda_fp16.h>
#include <cstdint>

// Round 14: fp16 HMMA (m16n8k16, fp32 accum) packed-fragment GEMMs.
// fp16 mantissa == tf32 mantissa (10 bits) and all values are O(1) -> same
// rel_err as the tf32 path, at 2x flops/instr and half the operand bytes.
//   prep: round W1/W2/x to fp16 and pack into m16n8k16 fragment order (u32 = half2).
//   K1: Hth = packedB( silu(W1 @ X + b1) )    CTA 128(f) x 128(l), K=256
//   K2: y   = W2 @ Ht + b2                    CTA 128(c) x 128(l), K=1024
// Warp tile 64x32 (2Mx4N warps), 4-stage cp.async ring, 2 CTAs/SM.
//
// Packed chunk = 32 k-values x 128 rows of fp16 = 2048 u32 (8 KB), 2 k0-steps (k16).
//   A[k0][m8][lane][4] u32: j0={A[m16g][2tg],+1} j1={A[+8][2tg],+1}
//                           j2={A[g][8+2tg],+1}  j3={A[+8][8+2tg],+1}
//   B[k0][nb][lane][2] u32: j0={B[nb8+g][2tg],+1} j1={B[nb8+g][8+2tg],+1}   (B[n][k])

namespace {

constexpr int E_ = 16, C_ = 256, F_ = 1024, L_ = 1024, B_ = 8;
constexpr int CH = 2048;  // u32 per packed chunk (8 KB)

__device__ uint32_t g_W1h[(size_t)E_ * 8 * 8 * CH];     //   8 MB
__device__ uint32_t g_W2h[(size_t)E_ * 2 * 32 * CH];    //   8 MB
__device__ uint32_t g_Xh [(size_t)B_ * E_ * 8 * 8 * CH];  //  64 MB
__device__ uint32_t g_Hth[(size_t)B_ * E_ * 8 * 32 * CH]; // 256 MB

__device__ __forceinline__ uint32_t packh2(float lo, float hi) {
    __half2 h = __floats2half2_rn(lo, hi);
    return *reinterpret_cast<uint32_t*>(&h);
}

__device__ __forceinline__ void mma_f16(float* d, const unsigned* a,
                                        unsigned b0, unsigned b1) {
    asm volatile(
        "mma.sync.aligned.m16n8k16.row.col.f32.f16.f16.f32 "
        "{%0,%1,%2,%3}, {%4,%5,%6,%7}, {%8,%9}, {%0,%1,%2,%3};\n"
        : "+f"(d[0]), "+f"(d[1]), "+f"(d[2]), "+f"(d[3])
        : "r"(a[0]), "r"(a[1]), "r"(a[2]), "r"(a[3]), "r"(b0), "r"(b1));
}
__device__ __forceinline__ uint32_t smem_u32(const void* p) {
    uint32_t a;
    asm("{ .reg .u64 t; cvta.to.shared.u64 t, %1; cvt.u32.u64 %0, t; }" : "=r"(a) : "l"(p));
    return a;
}
__device__ __forceinline__ void cp16(uint32_t dst, const void* src) {
    asm volatile("cp.async.cg.shared.global [%0], [%1], 16;\n" :: "r"(dst), "l"(src));
}
__device__ __forceinline__ void cp_commit() { asm volatile("cp.async.commit_group;\n"); }
template <int N> __device__ __forceinline__ void cp_wait() {
    asm volatile("cp.async.wait_group %0;\n" :: "n"(N));
}

constexpr int STAGE_U32 = 2 * CH;                          // A + B = 16 KB
constexpr size_t MAIN_SMEM = (size_t)(4 * STAGE_U32) * 4;  // 65536 B -> 2 CTAs/SM
constexpr int STGH_STR = 136;  // K1 staging [l=128][f=128] halves (34.8 KB)

}  // namespace

// ===================== prep kernels =====================
// A-type pack (W1/W2): src row-major [128 rows][K], one 8KB chunk per kc of 32.
__device__ __forceinline__ void pack_a_chunk(const float (*ws)[36], uint32_t* dst, int tid) {
    #pragma unroll
    for (int it = 0; it < 2; it++) {
        const int i4 = tid + it * 256;                  // [0,512)
        const int k0 = i4 >> 8, m8 = (i4 >> 5) & 7, ln = i4 & 31;
        const int g = ln >> 2, tg = ln & 3;
        const int kb = k0 * 16 + 2 * tg;
        uint4 v;
        v.x = packh2(ws[m8 * 16 + g][kb],     ws[m8 * 16 + g][kb + 1]);
        v.y = packh2(ws[m8 * 16 + 8 + g][kb], ws[m8 * 16 + 8 + g][kb + 1]);
        v.z = packh2(ws[m8 * 16 + g][kb + 8],     ws[m8 * 16 + g][kb + 9]);
        v.w = packh2(ws[m8 * 16 + 8 + g][kb + 8], ws[m8 * 16 + 8 + g][kb + 9]);
        *(uint4*)(dst + (size_t)i4 * 4) = v;
    }
}

__global__ __launch_bounds__(256, 4)
void prep_w1(const float* __restrict__ W1) {
    __shared__ float ws[128][36];
    const int e = blockIdx.y, ft = blockIdx.x, tid = threadIdx.x;
    const float* src = W1 + (size_t)(e * F_ + ft * 128) * C_;
    uint32_t* dst = g_W1h + ((size_t)(e * 8 + ft) * 8) * CH;
    for (int kc = 0; kc < 8; kc++) {
        __syncthreads();
        #pragma unroll
        for (int it = 0; it < 4; it++) {
            const int idx = tid + it * 256, r = idx >> 3, c4 = (idx & 7) * 4;
            const float4 v = *(const float4*)(src + (size_t)r * C_ + kc * 32 + c4);
            ws[r][c4] = v.x; ws[r][c4 + 1] = v.y; ws[r][c4 + 2] = v.z; ws[r][c4 + 3] = v.w;
        }
        __syncthreads();
        pack_a_chunk(ws, dst + (size_t)kc * CH, tid);
    }
}

__global__ __launch_bounds__(256, 4)
void prep_w2(const float* __restrict__ W2) {
    __shared__ float ws[128][36];
    const int e = blockIdx.y, cb = blockIdx.x, tid = threadIdx.x;
    const float* src = W2 + (size_t)(e * C_ + cb * 128) * F_;
    uint32_t* dst = g_W2h + ((size_t)(e * 2 + cb) * 32) * CH;
    for (int kc = 0; kc < 32; kc++) {
        __syncthreads();
        #pragma unroll
        for (int it = 0; it < 4; it++) {
            const int idx = tid + it * 256, r = idx >> 3, f4 = (idx & 7) * 4;
            const float4 v = *(const float4*)(src + (size_t)r * F_ + kc * 32 + f4);
            ws[r][f4] = v.x; ws[r][f4 + 1] = v.y; ws[r][f4 + 2] = v.z; ws[r][f4 + 3] = v.w;
        }
        __syncthreads();
        pack_a_chunk(ws, dst + (size_t)kc * CH, tid);
    }
}

// B-type pack (x): n = l, k = c (pairs span two c-rows).
__global__ __launch_bounds__(256, 4)
void prep_x(const float* __restrict__ x) {
    __shared__ float xs[32][132];
    const int p = blockIdx.y, lt = blockIdx.x, tid = threadIdx.x;
    const float* src = x + (size_t)p * C_ * L_ + lt * 128;
    uint32_t* dst = g_Xh + ((size_t)(p * 8 + lt) * 8) * CH;
    for (int kc = 0; kc < 8; kc++) {
        __syncthreads();
        #pragma unroll
        for (int it = 0; it < 4; it++) {
            const int idx = tid + it * 256, c = idx >> 5, l4 = (idx & 31) * 4;
            const float4 v = *(const float4*)(src + (size_t)(kc * 32 + c) * L_ + l4);
            xs[c][l4] = v.x; xs[c][l4 + 1] = v.y; xs[c][l4 + 2] = v.z; xs[c][l4 + 3] = v.w;
        }
        __syncthreads();
        #pragma unroll
        for (int it = 0; it < 4; it++) {
            const int i2 = tid + it * 256;              // [0,1024)
            const int k0 = i2 >> 9, nb = (i2 >> 5) & 15, ln = i2 & 31;
            const int g = ln >> 2, tg = ln & 3;
            const int kb = k0 * 16 + 2 * tg, n = nb * 8 + g;
            uint2 v;
            v.x = packh2(xs[kb][n],     xs[kb + 1][n]);
            v.y = packh2(xs[kb + 8][n], xs[kb + 9][n]);
            *(uint2*)(dst + (size_t)kc * CH + (size_t)i2 * 2) = v;
        }
    }
}

// ===================== K1: Hth = packedB(silu(W1 @ X + b1)) =====================
__global__ __launch_bounds__(256, 2)
void experts_k1(const float* __restrict__ b1) {
    extern __shared__ uint32_t smu[];
    const uint32_t sm_u = smem_u32(smu);

    const int tid = threadIdx.x, warp = tid >> 5, lane = tid & 31;
    const int g = lane >> 2, tg = lane & 3;
    const int p = blockIdx.z, e = p & (E_ - 1);
    const int ft = blockIdx.y, lt = blockIdx.x;

    const uint32_t* Aglob = g_W1h + ((size_t)(e * 8 + ft) * 8) * CH;
    const uint32_t* Bglob = g_Xh + ((size_t)(p * 8 + lt) * 8) * CH;

    const int warpM = warp >> 2, warpN = warp & 3;  // 2x4: warp tile 64(f) x 32(l)

    auto load_chunk = [&](int kc, int buf) {
        const uint32_t sd = sm_u + (uint32_t)(buf * STAGE_U32) * 4;
        const uint32_t* as = Aglob + (size_t)kc * CH;
        const uint32_t* bs = Bglob + (size_t)kc * CH;
        #pragma unroll
        for (int it = 0; it < 2; it++) {
            const int i4 = tid + it * 256;
            cp16(sd + (uint32_t)i4 * 16, as + (size_t)i4 * 4);
            cp16(sd + (uint32_t)(CH + i4 * 4) * 4, bs + (size_t)i4 * 4);
        }
    };

    float acc[4][4][4];
    #pragma unroll
    for (int mi = 0; mi < 4; mi++)
        #pragma unroll
        for (int ni = 0; ni < 4; ni++)
            #pragma unroll
            for (int r = 0; r < 4; r++) acc[mi][ni][r] = 0.f;

    load_chunk(0, 0); cp_commit();
    load_chunk(1, 1); cp_commit();
    load_chunk(2, 2); cp_commit();

    for (int kc = 0; kc < 8; kc++) {
        cp_wait<2>();
        __syncthreads();
        if (kc + 3 < 8) load_chunk(kc + 3, (kc + 3) & 3);
        cp_commit();

        const uint32_t* Ab = smu + (kc & 3) * STAGE_U32;
        const uint32_t* Bb = Ab + CH;
        #pragma unroll
        for (int k0 = 0; k0 < 2; k0++) {
            uint4 av[4];
            #pragma unroll
            for (int mi = 0; mi < 4; mi++)
                av[mi] = *(const uint4*)(Ab + ((k0 * 8 + warpM * 4 + mi) * 32 + lane) * 4);
            uint2 bv[4];
            #pragma unroll
            for (int ni = 0; ni < 4; ni++)
                bv[ni] = *(const uint2*)(Bb + ((k0 * 16 + warpN * 4 + ni) * 32 + lane) * 2);
            #pragma unroll
            for (int ni = 0; ni < 4; ni++)
                #pragma unroll
                for (int mi = 0; mi < 4; mi++)
                    mma_f16(acc[mi][ni], (const unsigned*)&av[mi], bv[ni].x, bv[ni].y);
        }
    }
    cp_wait<0>();
    __syncthreads();  // pipeline buffers free -> staging

    float bias[4][2];
    #pragma unroll
    for (int mi = 0; mi < 4; mi++)
        #pragma unroll
        for (int hi = 0; hi < 2; hi++)
            bias[mi][hi] = __ldg(b1 + e * F_ + ft * 128 + (warpM * 4 + mi) * 16 + g + hi * 8);

    __half* stg = reinterpret_cast<__half*>(smu);  // [l=128][STGH_STR] halves
    #pragma unroll
    for (int mi = 0; mi < 4; mi++)
        #pragma unroll
        for (int ni = 0; ni < 4; ni++)
            #pragma unroll
            for (int r = 0; r < 4; r++) {
                const int fL = (warpM * 4 + mi) * 16 + g + ((r >> 1) << 3);
                const int l = warpN * 32 + ni * 8 + tg * 2 + (r & 1);
                float v = acc[mi][ni][r] + bias[mi][r >> 1];
                v = v / (1.f + __expf(-v));  // silu
                stg[l * STGH_STR + fL] = __float2half_rn(v);
            }
    __syncthreads();

    // emit Ht in K2's packed-B layout; this CTA covers kc' in [ft*4, ft*4+4)
    uint32_t* dst = g_Hth + ((size_t)(p * 8 + lt) * 32 + ft * 4) * CH;
    #pragma unroll
    for (int it = 0; it < 16; it++) {
        const int i2 = tid + it * 256;               // [0, 4096)
        const int kcL = i2 >> 10, rem = i2 & 1023;
        const int k0 = rem >> 9, nb = (rem >> 5) & 15, ln = rem & 31;
        const int gg = ln >> 2, tt = ln & 3;
        const int l = nb * 8 + gg;
        const int fb = kcL * 32 + k0 * 16 + 2 * tt;  // even -> u32-aligned half2 read
        uint2 v;
        v.x = *(const uint32_t*)(stg + l * STGH_STR + fb);
        v.y = *(const uint32_t*)(stg + l * STGH_STR + fb + 8);
        *(uint2*)(dst + (size_t)kcL * CH + (size_t)rem * 2) = v;
    }
}

// ===================== K2: y = W2 @ Ht + b2 =====================
__global__ __launch_bounds__(256, 2)
void experts_k2(const float* __restrict__ b2, float* __restrict__ y) {
    extern __shared__ uint32_t smu[];
    const uint32_t sm_u = smem_u32(smu);

    const int tid = threadIdx.x, warp = tid >> 5, lane = tid & 31;
    const int g = lane >> 2, tg = lane & 3;
    const int p = blockIdx.z, e = p & (E_ - 1);
    const int cb = blockIdx.y, lt = blockIdx.x;

    const uint32_t* Aglob = g_W2h + ((size_t)(e * 2 + cb) * 32) * CH;
    const uint32_t* Bglob = g_Hth + ((size_t)(p * 8 + lt) * 32) * CH;

    const int warpM = warp >> 2, warpN = warp & 3;  // 2x4: warp tile 64(c) x 32(l)

    auto load_chunk = [&](int kc, int buf) {
        const uint32_t sd = sm_u + (uint32_t)(buf * STAGE_U32) * 4;
        const uint32_t* as = Aglob + (size_t)kc * CH;
        const uint32_t* bs = Bglob + (size_t)kc * CH;
        #pragma unroll
        for (int it = 0; it < 2; it++) {
            const int i4 = tid + it * 256;
            cp16(sd + (uint32_t)i4 * 16, as + (size_t)i4 * 4);
            cp16(sd + (uint32_t)(CH + i4 * 4) * 4, bs + (size_t)i4 * 4);
        }
    };

    float acc[4][4][4];
    #pragma unroll
    for (int mi = 0; mi < 4; mi++)
        #pragma unroll
        for (int ni = 0; ni < 4; ni++)
            #pragma unroll
            for (int r = 0; r < 4; r++) acc[mi][ni][r] = 0.f;

    load_chunk(0, 0); cp_commit();
    load_chunk(1, 1); cp_commit();
    load_chunk(2, 2); cp_commit();

    for (int kc = 0; kc < 32; kc++) {
        cp_wait<2>();
        __syncthreads();
        if (kc + 3 < 32) load_chunk(kc + 3, (kc + 3) & 3);
        cp_commit();

        const uint32_t* Ab = smu + (kc & 3) * STAGE_U32;
        const uint32_t* Bb = Ab + CH;
        #pragma unroll
        for (int k0 = 0; k0 < 2; k0++) {
            uint4 av[4];
            #pragma unroll
            for (int mi = 0; mi < 4; mi++)
                av[mi] = *(const uint4*)(Ab + ((k0 * 8 + warpM * 4 + mi) * 32 + lane) * 4);
            uint2 bv[4];
            #pragma unroll
            for (int ni = 0; ni < 4; ni++)
                bv[ni] = *(const uint2*)(Bb + ((k0 * 16 + warpN * 4 + ni) * 32 + lane) * 2);
            #pragma unroll
            for (int ni = 0; ni < 4; ni++)
                #pragma unroll
                for (int mi = 0; mi < 4; mi++)
                    mma_f16(acc[mi][ni], (const unsigned*)&av[mi], bv[ni].x, bv[ni].y);
        }
    }

    // epilogue: + b2 -> y, direct float2 stores (each 32B sector fully covered
    // by the 4 tg lanes -> sector-efficient without smem staging)
    #pragma unroll
    for (int mi = 0; mi < 4; mi++) {
        #pragma unroll
        for (int r2 = 0; r2 < 2; r2++) {
            const int c = cb * 128 + (warpM * 4 + mi) * 16 + g + r2 * 8;
            const float bias = __ldg(b2 + e * C_ + c);
            float* yp = y + ((size_t)p * C_ + c) * L_ + lt * 128;
            #pragma unroll
            for (int ni = 0; ni < 4; ni++) {
                const int l = warpN * 32 + ni * 8 + tg * 2;
                float2 v;
                v.x = acc[mi][ni][r2 * 2 + 0] + bias;
                v.y = acc[mi][ni][r2 * 2 + 1] + bias;
                *(float2*)(yp + l) = v;
            }
        }
    }
}

extern "C" void kernel_launch(void* const* d_in, const int* in_sizes, int n_in,
                              void* d_out, int out_size) {
    const float* x  = (const float*)d_in[0];
    const float* W1 = (const float*)d_in[1];
    const float* b1 = (const float*)d_in[2];
    const float* W2 = (const float*)d_in[3];
    const float* b2 = (const float*)d_in[4];
    float* y = (float*)d_out;

    cudaFuncSetAttribute(experts_k1, cudaFuncAttributeMaxDynamicSharedMemorySize, (int)MAIN_SMEM);
    cudaFuncSetAttribute(experts_k2, cudaFuncAttributeMaxDynamicSharedMemorySize, (int)MAIN_SMEM);

    prep_x <<<dim3(8, B_ * E_), 256>>>(x);     // 1024 CTAs
    prep_w1<<<dim3(8, E_), 256>>>(W1);         //  128 CTAs
    prep_w2<<<dim3(2, E_), 256>>>(W2);         //   32 CTAs

    experts_k1<<<dim3(8, 8, B_ * E_), 256, MAIN_SMEM>>>(b1);        // 8192 CTAs
    experts_k2<<<dim3(8, 2, B_ * E_), 256, MAIN_SMEM>>>(b2, y);     // 2048 CTAs
}

// round 16
// speedup vs baseline: 1.7160x; 1.0009x over previous
#include <cuda_runtime.h>
#include <cuda_fp16.h>
#include <cstdint>

// Round 15: fp16 HMMA packed-fragment GEMMs + software-pipelined fragments.
// Per kc iteration: ALL fragment LDS issued up front (B both k0, A k0=0,
// cp.async prefetch, A k0=1), then 32 back-to-back MMAs -- removes the
// per-k0 LDS->MMA dependency stall that left tensor at 43%.
//   K1: Hth = packedB( silu(W1 @ X + b1) )    CTA 128(f) x 128(l), K=256
//   K2: y   = W2 @ Ht + b2                    CTA 128(c) x 128(l), K=1024
// Warp tile 64x32 (2Mx4N), 4-stage cp.async ring, 2 CTAs/SM.
//
// Packed chunk = 32 k x 128 rows fp16 = 2048 u32 (8 KB), 2 k0-steps (k16).
//   A[k0][m8][lane][4] u32, B[k0][nb][lane][2] u32 (see prep kernels).

namespace {

constexpr int E_ = 16, C_ = 256, F_ = 1024, L_ = 1024, B_ = 8;
constexpr int CH = 2048;  // u32 per packed chunk (8 KB)

__device__ uint32_t g_W1h[(size_t)E_ * 8 * 8 * CH];       //   8 MB
__device__ uint32_t g_W2h[(size_t)E_ * 2 * 32 * CH];      //   8 MB
__device__ uint32_t g_Xh [(size_t)B_ * E_ * 8 * 8 * CH];  //  64 MB
__device__ uint32_t g_Hth[(size_t)B_ * E_ * 8 * 32 * CH]; // 256 MB

__device__ __forceinline__ uint32_t packh2(float lo, float hi) {
    __half2 h = __floats2half2_rn(lo, hi);
    return *reinterpret_cast<uint32_t*>(&h);
}

__device__ __forceinline__ void mma_f16(float* d, const unsigned* a,
                                        unsigned b0, unsigned b1) {
    asm volatile(
        "mma.sync.aligned.m16n8k16.row.col.f32.f16.f16.f32 "
        "{%0,%1,%2,%3}, {%4,%5,%6,%7}, {%8,%9}, {%0,%1,%2,%3};\n"
        : "+f"(d[0]), "+f"(d[1]), "+f"(d[2]), "+f"(d[3])
        : "r"(a[0]), "r"(a[1]), "r"(a[2]), "r"(a[3]), "r"(b0), "r"(b1));
}
__device__ __forceinline__ uint32_t smem_u32(const void* p) {
    uint32_t a;
    asm("{ .reg .u64 t; cvta.to.shared.u64 t, %1; cvt.u32.u64 %0, t; }" : "=r"(a) : "l"(p));
    return a;
}
__device__ __forceinline__ void cp16(uint32_t dst, const void* src) {
    asm volatile("cp.async.cg.shared.global [%0], [%1], 16;\n" :: "r"(dst), "l"(src));
}
__device__ __forceinline__ void cp_commit() { asm volatile("cp.async.commit_group;\n"); }
template <int N> __device__ __forceinline__ void cp_wait() {
    asm volatile("cp.async.wait_group %0;\n" :: "n"(N));
}

constexpr int STAGE_U32 = 2 * CH;                          // A + B = 16 KB
constexpr size_t MAIN_SMEM = (size_t)(4 * STAGE_U32) * 4;  // 65536 B -> 2 CTAs/SM
constexpr int STGH_STR = 136;  // K1 staging [l=128][f=128] halves (34.8 KB)

}  // namespace

// ===================== prep kernels =====================
__device__ __forceinline__ void pack_a_chunk(const float (*ws)[36], uint32_t* dst, int tid) {
    #pragma unroll
    for (int it = 0; it < 2; it++) {
        const int i4 = tid + it * 256;                  // [0,512)
        const int k0 = i4 >> 8, m8 = (i4 >> 5) & 7, ln = i4 & 31;
        const int g = ln >> 2, tg = ln & 3;
        const int kb = k0 * 16 + 2 * tg;
        uint4 v;
        v.x = packh2(ws[m8 * 16 + g][kb],     ws[m8 * 16 + g][kb + 1]);
        v.y = packh2(ws[m8 * 16 + 8 + g][kb], ws[m8 * 16 + 8 + g][kb + 1]);
        v.z = packh2(ws[m8 * 16 + g][kb + 8],     ws[m8 * 16 + g][kb + 9]);
        v.w = packh2(ws[m8 * 16 + 8 + g][kb + 8], ws[m8 * 16 + 8 + g][kb + 9]);
        *(uint4*)(dst + (size_t)i4 * 4) = v;
    }
}

__global__ __launch_bounds__(256, 4)
void prep_w1(const float* __restrict__ W1) {
    __shared__ float ws[128][36];
    const int e = blockIdx.y, ft = blockIdx.x, tid = threadIdx.x;
    const float* src = W1 + (size_t)(e * F_ + ft * 128) * C_;
    uint32_t* dst = g_W1h + ((size_t)(e * 8 + ft) * 8) * CH;
    for (int kc = 0; kc < 8; kc++) {
        __syncthreads();
        #pragma unroll
        for (int it = 0; it < 4; it++) {
            const int idx = tid + it * 256, r = idx >> 3, c4 = (idx & 7) * 4;
            const float4 v = *(const float4*)(src + (size_t)r * C_ + kc * 32 + c4);
            ws[r][c4] = v.x; ws[r][c4 + 1] = v.y; ws[r][c4 + 2] = v.z; ws[r][c4 + 3] = v.w;
        }
        __syncthreads();
        pack_a_chunk(ws, dst + (size_t)kc * CH, tid);
    }
}

__global__ __launch_bounds__(256, 4)
void prep_w2(const float* __restrict__ W2) {
    __shared__ float ws[128][36];
    const int e = blockIdx.y, cb = blockIdx.x, tid = threadIdx.x;
    const float* src = W2 + (size_t)(e * C_ + cb * 128) * F_;
    uint32_t* dst = g_W2h + ((size_t)(e * 2 + cb) * 32) * CH;
    for (int kc = 0; kc < 32; kc++) {
        __syncthreads();
        #pragma unroll
        for (int it = 0; it < 4; it++) {
            const int idx = tid + it * 256, r = idx >> 3, f4 = (idx & 7) * 4;
            const float4 v = *(const float4*)(src + (size_t)r * F_ + kc * 32 + f4);
            ws[r][f4] = v.x; ws[r][f4 + 1] = v.y; ws[r][f4 + 2] = v.z; ws[r][f4 + 3] = v.w;
        }
        __syncthreads();
        pack_a_chunk(ws, dst + (size_t)kc * CH, tid);
    }
}

__global__ __launch_bounds__(256, 4)
void prep_x(const float* __restrict__ x) {
    __shared__ float xs[32][132];
    const int p = blockIdx.y, lt = blockIdx.x, tid = threadIdx.x;
    const float* src = x + (size_t)p * C_ * L_ + lt * 128;
    uint32_t* dst = g_Xh + ((size_t)(p * 8 + lt) * 8) * CH;
    for (int kc = 0; kc < 8; kc++) {
        __syncthreads();
        #pragma unroll
        for (int it = 0; it < 4; it++) {
            const int idx = tid + it * 256, c = idx >> 5, l4 = (idx & 31) * 4;
            const float4 v = *(const float4*)(src + (size_t)(kc * 32 + c) * L_ + l4);
            xs[c][l4] = v.x; xs[c][l4 + 1] = v.y; xs[c][l4 + 2] = v.z; xs[c][l4 + 3] = v.w;
        }
        __syncthreads();
        #pragma unroll
        for (int it = 0; it < 4; it++) {
            const int i2 = tid + it * 256;              // [0,1024)
            const int k0 = i2 >> 9, nb = (i2 >> 5) & 15, ln = i2 & 31;
            const int g = ln >> 2, tg = ln & 3;
            const int kb = k0 * 16 + 2 * tg, n = nb * 8 + g;
            uint2 v;
            v.x = packh2(xs[kb][n],     xs[kb + 1][n]);
            v.y = packh2(xs[kb + 8][n], xs[kb + 9][n]);
            *(uint2*)(dst + (size_t)kc * CH + (size_t)i2 * 2) = v;
        }
    }
}

// ===================== K1: Hth = packedB(silu(W1 @ X + b1)) =====================
__global__ __launch_bounds__(256, 2)
void experts_k1(const float* __restrict__ b1) {
    extern __shared__ uint32_t smu[];
    const uint32_t sm_u = smem_u32(smu);

    const int tid = threadIdx.x, warp = tid >> 5, lane = tid & 31;
    const int g = lane >> 2, tg = lane & 3;
    const int p = blockIdx.z, e = p & (E_ - 1);
    const int ft = blockIdx.y, lt = blockIdx.x;

    const uint32_t* Aglob = g_W1h + ((size_t)(e * 8 + ft) * 8) * CH;
    const uint32_t* Bglob = g_Xh + ((size_t)(p * 8 + lt) * 8) * CH;

    const int warpM = warp >> 2, warpN = warp & 3;  // 2x4: warp tile 64(f) x 32(l)

    auto load_chunk = [&](int kc, int buf) {
        const uint32_t sd = sm_u + (uint32_t)(buf * STAGE_U32) * 4;
        const uint32_t* as = Aglob + (size_t)kc * CH;
        const uint32_t* bs = Bglob + (size_t)kc * CH;
        #pragma unroll
        for (int it = 0; it < 2; it++) {
            const int i4 = tid + it * 256;
            cp16(sd + (uint32_t)i4 * 16, as + (size_t)i4 * 4);
            cp16(sd + (uint32_t)(CH + i4 * 4) * 4, bs + (size_t)i4 * 4);
        }
    };

    float acc[4][4][4];
    #pragma unroll
    for (int mi = 0; mi < 4; mi++)
        #pragma unroll
        for (int ni = 0; ni < 4; ni++)
            #pragma unroll
            for (int r = 0; r < 4; r++) acc[mi][ni][r] = 0.f;

    load_chunk(0, 0); cp_commit();
    load_chunk(1, 1); cp_commit();
    load_chunk(2, 2); cp_commit();

    for (int kc = 0; kc < 8; kc++) {
        cp_wait<2>();
        __syncthreads();

        const uint32_t* Ab = smu + (kc & 3) * STAGE_U32;
        const uint32_t* Bb = Ab + CH;

        // --- front-load ALL fragments for this chunk ---
        uint2 bv[2][4];
        #pragma unroll
        for (int k0 = 0; k0 < 2; k0++)
            #pragma unroll
            for (int ni = 0; ni < 4; ni++)
                bv[k0][ni] = *(const uint2*)(Bb + ((k0 * 16 + warpN * 4 + ni) * 32 + lane) * 2);
        uint4 av[2][4];
        #pragma unroll
        for (int mi = 0; mi < 4; mi++)
            av[0][mi] = *(const uint4*)(Ab + ((warpM * 4 + mi) * 32 + lane) * 4);

        if (kc + 3 < 8) load_chunk(kc + 3, (kc + 3) & 3);
        cp_commit();

        #pragma unroll
        for (int mi = 0; mi < 4; mi++)
            av[1][mi] = *(const uint4*)(Ab + ((8 + warpM * 4 + mi) * 32 + lane) * 4);

        // --- 32 back-to-back MMAs ---
        #pragma unroll
        for (int k0 = 0; k0 < 2; k0++)
            #pragma unroll
            for (int ni = 0; ni < 4; ni++)
                #pragma unroll
                for (int mi = 0; mi < 4; mi++)
                    mma_f16(acc[mi][ni], (const unsigned*)&av[k0][mi],
                            bv[k0][ni].x, bv[k0][ni].y);
    }
    cp_wait<0>();
    __syncthreads();  // pipeline buffers free -> staging

    float bias[4][2];
    #pragma unroll
    for (int mi = 0; mi < 4; mi++)
        #pragma unroll
        for (int hi = 0; hi < 2; hi++)
            bias[mi][hi] = __ldg(b1 + e * F_ + ft * 128 + (warpM * 4 + mi) * 16 + g + hi * 8);

    __half* stg = reinterpret_cast<__half*>(smu);  // [l=128][STGH_STR] halves
    #pragma unroll
    for (int mi = 0; mi < 4; mi++)
        #pragma unroll
        for (int ni = 0; ni < 4; ni++)
            #pragma unroll
            for (int r = 0; r < 4; r++) {
                const int fL = (warpM * 4 + mi) * 16 + g + ((r >> 1) << 3);
                const int l = warpN * 32 + ni * 8 + tg * 2 + (r & 1);
                float v = acc[mi][ni][r] + bias[mi][r >> 1];
                v = v / (1.f + __expf(-v));  // silu
                stg[l * STGH_STR + fL] = __float2half_rn(v);
            }
    __syncthreads();

    // emit Ht in K2's packed-B layout; this CTA covers kc' in [ft*4, ft*4+4)
    uint32_t* dst = g_Hth + ((size_t)(p * 8 + lt) * 32 + ft * 4) * CH;
    #pragma unroll
    for (int it = 0; it < 16; it++) {
        const int i2 = tid + it * 256;               // [0, 4096)
        const int kcL = i2 >> 10, rem = i2 & 1023;
        const int k0 = rem >> 9, nb = (rem >> 5) & 15, ln = rem & 31;
        const int gg = ln >> 2, tt = ln & 3;
        const int l = nb * 8 + gg;
        const int fb = kcL * 32 + k0 * 16 + 2 * tt;  // even -> u32-aligned half2 read
        uint2 v;
        v.x = *(const uint32_t*)(stg + l * STGH_STR + fb);
        v.y = *(const uint32_t*)(stg + l * STGH_STR + fb + 8);
        *(uint2*)(dst + (size_t)kcL * CH + (size_t)rem * 2) = v;
    }
}

// ===================== K2: y = W2 @ Ht + b2 =====================
__global__ __launch_bounds__(256, 2)
void experts_k2(const float* __restrict__ b2, float* __restrict__ y) {
    extern __shared__ uint32_t smu[];
    const uint32_t sm_u = smem_u32(smu);

    const int tid = threadIdx.x, warp = tid >> 5, lane = tid & 31;
    const int g = lane >> 2, tg = lane & 3;
    const int p = blockIdx.z, e = p & (E_ - 1);
    const int cb = blockIdx.y, lt = blockIdx.x;

    const uint32_t* Aglob = g_W2h + ((size_t)(e * 2 + cb) * 32) * CH;
    const uint32_t* Bglob = g_Hth + ((size_t)(p * 8 + lt) * 32) * CH;

    const int warpM = warp >> 2, warpN = warp & 3;  // 2x4: warp tile 64(c) x 32(l)

    auto load_chunk = [&](int kc, int buf) {
        const uint32_t sd = sm_u + (uint32_t)(buf * STAGE_U32) * 4;
        const uint32_t* as = Aglob + (size_t)kc * CH;
        const uint32_t* bs = Bglob + (size_t)kc * CH;
        #pragma unroll
        for (int it = 0; it < 2; it++) {
            const int i4 = tid + it * 256;
            cp16(sd + (uint32_t)i4 * 16, as + (size_t)i4 * 4);
            cp16(sd + (uint32_t)(CH + i4 * 4) * 4, bs + (size_t)i4 * 4);
        }
    };

    float acc[4][4][4];
    #pragma unroll
    for (int mi = 0; mi < 4; mi++)
        #pragma unroll
        for (int ni = 0; ni < 4; ni++)
            #pragma unroll
            for (int r = 0; r < 4; r++) acc[mi][ni][r] = 0.f;

    load_chunk(0, 0); cp_commit();
    load_chunk(1, 1); cp_commit();
    load_chunk(2, 2); cp_commit();

    for (int kc = 0; kc < 32; kc++) {
        cp_wait<2>();
        __syncthreads();

        const uint32_t* Ab = smu + (kc & 3) * STAGE_U32;
        const uint32_t* Bb = Ab + CH;

        uint2 bv[2][4];
        #pragma unroll
        for (int k0 = 0; k0 < 2; k0++)
            #pragma unroll
            for (int ni = 0; ni < 4; ni++)
                bv[k0][ni] = *(const uint2*)(Bb + ((k0 * 16 + warpN * 4 + ni) * 32 + lane) * 2);
        uint4 av[2][4];
        #pragma unroll
        for (int mi = 0; mi < 4; mi++)
            av[0][mi] = *(const uint4*)(Ab + ((warpM * 4 + mi) * 32 + lane) * 4);

        if (kc + 3 < 32) load_chunk(kc + 3, (kc + 3) & 3);
        cp_commit();

        #pragma unroll
        for (int mi = 0; mi < 4; mi++)
            av[1][mi] = *(const uint4*)(Ab + ((8 + warpM * 4 + mi) * 32 + lane) * 4);

        #pragma unroll
        for (int k0 = 0; k0 < 2; k0++)
            #pragma unroll
            for (int ni = 0; ni < 4; ni++)
                #pragma unroll
                for (int mi = 0; mi < 4; mi++)
                    mma_f16(acc[mi][ni], (const unsigned*)&av[k0][mi],
                            bv[k0][ni].x, bv[k0][ni].y);
    }

    // epilogue: + b2 -> y, direct float2 stores (sector-complete per tg group)
    #pragma unroll
    for (int mi = 0; mi < 4; mi++) {
        #pragma unroll
        for (int r2 = 0; r2 < 2; r2++) {
            const int c = cb * 128 + (warpM * 4 + mi) * 16 + g + r2 * 8;
            const float bias = __ldg(b2 + e * C_ + c);
            float* yp = y + ((size_t)p * C_ + c) * L_ + lt * 128;
            #pragma unroll
            for (int ni = 0; ni < 4; ni++) {
                const int l = warpN * 32 + ni * 8 + tg * 2;
                float2 v;
                v.x = acc[mi][ni][r2 * 2 + 0] + bias;
                v.y = acc[mi][ni][r2 * 2 + 1] + bias;
                *(float2*)(yp + l) = v;
            }
        }
    }
}

extern "C" void kernel_launch(void* const* d_in, const int* in_sizes, int n_in,
                              void* d_out, int out_size) {
    const float* x  = (const float*)d_in[0];
    const float* W1 = (const float*)d_in[1];
    const float* b1 = (const float*)d_in[2];
    const float* W2 = (const float*)d_in[3];
    const float* b2 = (const float*)d_in[4];
    float* y = (float*)d_out;

    cudaFuncSetAttribute(experts_k1, cudaFuncAttributeMaxDynamicSharedMemorySize, (int)MAIN_SMEM);
    cudaFuncSetAttribute(experts_k2, cudaFuncAttributeMaxDynamicSharedMemorySize, (int)MAIN_SMEM);

    prep_x <<<dim3(8, B_ * E_), 256>>>(x);     // 1024 CTAs
    prep_w1<<<dim3(8, E_), 256>>>(W1);         //  128 CTAs
    prep_w2<<<dim3(2, E_), 256>>>(W2);         //   32 CTAs

    experts_k1<<<dim3(8, 8, B_ * E_), 256, MAIN_SMEM>>>(b1);        // 8192 CTAs
    experts_k2<<<dim3(8, 2, B_ * E_), 256, MAIN_SMEM>>>(b2, y);     // 2048 CTAs
}

// round 17
// speedup vs baseline: 1.7892x; 1.0427x over previous
#include <cuda_runtime.h>
#include <cuda_fp16.h>
#include <cstdint>

// Round 16: fp16 HMMA packed-fragment GEMMs at 3 CTAs/SM.
// R15 post-mortem: fragment software-pipelining was a no-op (ptxas already did
// it) -- the kernel is latency-bound at 16 warps/SM. Trade warp-tile size for
// occupancy: warp tile 32x32 (acc 32 regs, ~75 total), CTA 128x64, 4-stage
// 12KB ring => 48KB/CTA, 3 CTAs/SM, 24 warps.
//   K1: Hth = packedB( silu(W1 @ X + b1) )    CTA 128(f) x 64(l), K=256
//   K2: y   = W2 @ Ht + b2                    CTA 128(c) x 64(l), K=1024
//
// Packed chunk = 32 k x 128 rows fp16 = 2048 u32 (8 KB), 2 k0-steps (k16).
//   A[k0][m8][lane][4] u32, B[k0][nb][lane][2] u32. A CTA consumes the full
//   A chunk (m=128) and one 64-l half of the B chunk (nb 8h..8h+8 per k0).

namespace {

constexpr int E_ = 16, C_ = 256, F_ = 1024, L_ = 1024, B_ = 8;
constexpr int CH = 2048;   // u32 per packed chunk (8 KB)
constexpr int BH = 1024;   // u32 per B half-chunk (4 KB)

__device__ uint32_t g_W1h[(size_t)E_ * 8 * 8 * CH];       //   8 MB
__device__ uint32_t g_W2h[(size_t)E_ * 2 * 32 * CH];      //   8 MB
__device__ uint32_t g_Xh [(size_t)B_ * E_ * 8 * 8 * CH];  //  64 MB
__device__ uint32_t g_Hth[(size_t)B_ * E_ * 8 * 32 * CH]; // 256 MB

__device__ __forceinline__ uint32_t packh2(float lo, float hi) {
    __half2 h = __floats2half2_rn(lo, hi);
    return *reinterpret_cast<uint32_t*>(&h);
}

__device__ __forceinline__ void mma_f16(float* d, const unsigned* a,
                                        unsigned b0, unsigned b1) {
    asm volatile(
        "mma.sync.aligned.m16n8k16.row.col.f32.f16.f16.f32 "
        "{%0,%1,%2,%3}, {%4,%5,%6,%7}, {%8,%9}, {%0,%1,%2,%3};\n"
        : "+f"(d[0]), "+f"(d[1]), "+f"(d[2]), "+f"(d[3])
        : "r"(a[0]), "r"(a[1]), "r"(a[2]), "r"(a[3]), "r"(b0), "r"(b1));
}
__device__ __forceinline__ uint32_t smem_u32(const void* p) {
    uint32_t a;
    asm("{ .reg .u64 t; cvta.to.shared.u64 t, %1; cvt.u32.u64 %0, t; }" : "=r"(a) : "l"(p));
    return a;
}
__device__ __forceinline__ void cp16(uint32_t dst, const void* src) {
    asm volatile("cp.async.cg.shared.global [%0], [%1], 16;\n" :: "r"(dst), "l"(src));
}
__device__ __forceinline__ void cp_commit() { asm volatile("cp.async.commit_group;\n"); }
template <int N> __device__ __forceinline__ void cp_wait() {
    asm volatile("cp.async.wait_group %0;\n" :: "n"(N));
}

constexpr int STAGE_U32 = CH + BH;                         // A 8KB + B-half 4KB
constexpr size_t MAIN_SMEM = (size_t)(4 * STAGE_U32) * 4;  // 49152 B -> 3 CTAs/SM
constexpr int STGH_STR = 136;  // K1 staging [l=64][f=128] halves (17.4 KB)

}  // namespace

// ===================== prep kernels (unchanged) =====================
__device__ __forceinline__ void pack_a_chunk(const float (*ws)[36], uint32_t* dst, int tid) {
    #pragma unroll
    for (int it = 0; it < 2; it++) {
        const int i4 = tid + it * 256;                  // [0,512)
        const int k0 = i4 >> 8, m8 = (i4 >> 5) & 7, ln = i4 & 31;
        const int g = ln >> 2, tg = ln & 3;
        const int kb = k0 * 16 + 2 * tg;
        uint4 v;
        v.x = packh2(ws[m8 * 16 + g][kb],     ws[m8 * 16 + g][kb + 1]);
        v.y = packh2(ws[m8 * 16 + 8 + g][kb], ws[m8 * 16 + 8 + g][kb + 1]);
        v.z = packh2(ws[m8 * 16 + g][kb + 8],     ws[m8 * 16 + g][kb + 9]);
        v.w = packh2(ws[m8 * 16 + 8 + g][kb + 8], ws[m8 * 16 + 8 + g][kb + 9]);
        *(uint4*)(dst + (size_t)i4 * 4) = v;
    }
}

__global__ __launch_bounds__(256, 4)
void prep_w1(const float* __restrict__ W1) {
    __shared__ float ws[128][36];
    const int e = blockIdx.y, ft = blockIdx.x, tid = threadIdx.x;
    const float* src = W1 + (size_t)(e * F_ + ft * 128) * C_;
    uint32_t* dst = g_W1h + ((size_t)(e * 8 + ft) * 8) * CH;
    for (int kc = 0; kc < 8; kc++) {
        __syncthreads();
        #pragma unroll
        for (int it = 0; it < 4; it++) {
            const int idx = tid + it * 256, r = idx >> 3, c4 = (idx & 7) * 4;
            const float4 v = *(const float4*)(src + (size_t)r * C_ + kc * 32 + c4);
            ws[r][c4] = v.x; ws[r][c4 + 1] = v.y; ws[r][c4 + 2] = v.z; ws[r][c4 + 3] = v.w;
        }
        __syncthreads();
        pack_a_chunk(ws, dst + (size_t)kc * CH, tid);
    }
}

__global__ __launch_bounds__(256, 4)
void prep_w2(const float* __restrict__ W2) {
    __shared__ float ws[128][36];
    const int e = blockIdx.y, cb = blockIdx.x, tid = threadIdx.x;
    const float* src = W2 + (size_t)(e * C_ + cb * 128) * F_;
    uint32_t* dst = g_W2h + ((size_t)(e * 2 + cb) * 32) * CH;
    for (int kc = 0; kc < 32; kc++) {
        __syncthreads();
        #pragma unroll
        for (int it = 0; it < 4; it++) {
            const int idx = tid + it * 256, r = idx >> 3, f4 = (idx & 7) * 4;
            const float4 v = *(const float4*)(src + (size_t)r * F_ + kc * 32 + f4);
            ws[r][f4] = v.x; ws[r][f4 + 1] = v.y; ws[r][f4 + 2] = v.z; ws[r][f4 + 3] = v.w;
        }
        __syncthreads();
        pack_a_chunk(ws, dst + (size_t)kc * CH, tid);
    }
}

__global__ __launch_bounds__(256, 4)
void prep_x(const float* __restrict__ x) {
    __shared__ float xs[32][132];
    const int p = blockIdx.y, lt = blockIdx.x, tid = threadIdx.x;
    const float* src = x + (size_t)p * C_ * L_ + lt * 128;
    uint32_t* dst = g_Xh + ((size_t)(p * 8 + lt) * 8) * CH;
    for (int kc = 0; kc < 8; kc++) {
        __syncthreads();
        #pragma unroll
        for (int it = 0; it < 4; it++) {
            const int idx = tid + it * 256, c = idx >> 5, l4 = (idx & 31) * 4;
            const float4 v = *(const float4*)(src + (size_t)(kc * 32 + c) * L_ + l4);
            xs[c][l4] = v.x; xs[c][l4 + 1] = v.y; xs[c][l4 + 2] = v.z; xs[c][l4 + 3] = v.w;
        }
        __syncthreads();
        #pragma unroll
        for (int it = 0; it < 4; it++) {
            const int i2 = tid + it * 256;              // [0,1024)
            const int k0 = i2 >> 9, nb = (i2 >> 5) & 15, ln = i2 & 31;
            const int g = ln >> 2, tg = ln & 3;
            const int kb = k0 * 16 + 2 * tg, n = nb * 8 + g;
            uint2 v;
            v.x = packh2(xs[kb][n],     xs[kb + 1][n]);
            v.y = packh2(xs[kb + 8][n], xs[kb + 9][n]);
            *(uint2*)(dst + (size_t)kc * CH + (size_t)i2 * 2) = v;
        }
    }
}

// ===================== K1: Hth = packedB(silu(W1 @ X + b1)) =====================
__global__ __launch_bounds__(256, 3)
void experts_k1(const float* __restrict__ b1) {
    extern __shared__ uint32_t smu[];
    const uint32_t sm_u = smem_u32(smu);

    const int tid = threadIdx.x, warp = tid >> 5, lane = tid & 31;
    const int g = lane >> 2, tg = lane & 3;
    const int p = blockIdx.z, e = p & (E_ - 1);
    const int ft = blockIdx.y, lt64 = blockIdx.x;
    const int lt = lt64 >> 1, half = lt64 & 1;

    const uint32_t* Aglob = g_W1h + ((size_t)(e * 8 + ft) * 8) * CH;
    const uint32_t* Bglob = g_Xh + ((size_t)(p * 8 + lt) * 8) * CH;

    const int warpM = warp >> 1, warpN = warp & 1;  // 4x2: warp tile 32(f) x 32(l)

    auto load_chunk = [&](int kc, int buf) {
        const uint32_t sd = sm_u + (uint32_t)(buf * STAGE_U32) * 4;
        const uint32_t* as = Aglob + (size_t)kc * CH;
        #pragma unroll
        for (int it = 0; it < 2; it++) {            // A: 8 KB
            const int i4 = tid + it * 256;
            cp16(sd + (uint32_t)i4 * 16, as + (size_t)i4 * 4);
        }
        // B half: per k0, 512 contiguous u32 at (k0*16 + half*8)*64
        const int k0 = tid >> 7, off = (tid & 127) * 4;
        const uint32_t* bs = Bglob + (size_t)kc * CH + (k0 * 16 + half * 8) * 64;
        cp16(sd + (uint32_t)(CH + k0 * 512 + off) * 4, bs + off);
    };

    float acc[2][4][4];
    #pragma unroll
    for (int mi = 0; mi < 2; mi++)
        #pragma unroll
        for (int ni = 0; ni < 4; ni++)
            #pragma unroll
            for (int r = 0; r < 4; r++) acc[mi][ni][r] = 0.f;

    load_chunk(0, 0); cp_commit();
    load_chunk(1, 1); cp_commit();
    load_chunk(2, 2); cp_commit();

    for (int kc = 0; kc < 8; kc++) {
        cp_wait<2>();
        __syncthreads();
        if (kc + 3 < 8) load_chunk(kc + 3, (kc + 3) & 3);
        cp_commit();

        const uint32_t* Ab = smu + (kc & 3) * STAGE_U32;
        const uint32_t* Bb = Ab + CH;   // [k0][nbl 8][lane][2]
        #pragma unroll
        for (int k0 = 0; k0 < 2; k0++) {
            uint4 av[2];
            #pragma unroll
            for (int mi = 0; mi < 2; mi++)
                av[mi] = *(const uint4*)(Ab + ((k0 * 8 + warpM * 2 + mi) * 32 + lane) * 4);
            uint2 bv[4];
            #pragma unroll
            for (int ni = 0; ni < 4; ni++)
                bv[ni] = *(const uint2*)(Bb + ((k0 * 8 + warpN * 4 + ni) * 32 + lane) * 2);
            #pragma unroll
            for (int ni = 0; ni < 4; ni++)
                #pragma unroll
                for (int mi = 0; mi < 2; mi++)
                    mma_f16(acc[mi][ni], (const unsigned*)&av[mi], bv[ni].x, bv[ni].y);
        }
    }
    cp_wait<0>();
    __syncthreads();  // pipeline buffers free -> staging

    float bias[2][2];
    #pragma unroll
    for (int mi = 0; mi < 2; mi++)
        #pragma unroll
        for (int hi = 0; hi < 2; hi++)
            bias[mi][hi] = __ldg(b1 + e * F_ + ft * 128 + (warpM * 2 + mi) * 16 + g + hi * 8);

    __half* stg = reinterpret_cast<__half*>(smu);  // [l=64][STGH_STR] halves
    #pragma unroll
    for (int mi = 0; mi < 2; mi++)
        #pragma unroll
        for (int ni = 0; ni < 4; ni++)
            #pragma unroll
            for (int r = 0; r < 4; r++) {
                const int fL = (warpM * 2 + mi) * 16 + g + ((r >> 1) << 3);
                const int l = warpN * 32 + ni * 8 + tg * 2 + (r & 1);
                float v = acc[mi][ni][r] + bias[mi][r >> 1];
                v = v / (1.f + __expf(-v));  // silu
                stg[l * STGH_STR + fL] = __float2half_rn(v);
            }
    __syncthreads();

    // emit Ht in K2's packed-B layout; CTA covers kc' in [ft*4,ft*4+4), nb half
    uint32_t* dst = g_Hth + ((size_t)(p * 8 + lt) * 32 + ft * 4) * CH;
    #pragma unroll
    for (int it = 0; it < 8; it++) {
        const int i2 = tid + it * 256;               // [0, 2048)
        const int kcL = i2 >> 9, rem = i2 & 511;
        const int k0 = rem >> 8, nbl = (rem >> 5) & 7, ln = rem & 31;
        const int gg = ln >> 2, tt = ln & 3;
        const int l = nbl * 8 + gg;                  // local l in [0,64)
        const int fb = kcL * 32 + k0 * 16 + 2 * tt;  // even -> u32-aligned half2 read
        uint2 v;
        v.x = *(const uint32_t*)(stg + l * STGH_STR + fb);
        v.y = *(const uint32_t*)(stg + l * STGH_STR + fb + 8);
        *(uint2*)(dst + (size_t)kcL * CH + (k0 * 16 + half * 8 + nbl) * 64 + ln * 2) = v;
    }
}

// ===================== K2: y = W2 @ Ht + b2 =====================
__global__ __launch_bounds__(256, 3)
void experts_k2(const float* __restrict__ b2, float* __restrict__ y) {
    extern __shared__ uint32_t smu[];
    const uint32_t sm_u = smem_u32(smu);

    const int tid = threadIdx.x, warp = tid >> 5, lane = tid & 31;
    const int g = lane >> 2, tg = lane & 3;
    const int p = blockIdx.z, e = p & (E_ - 1);
    const int cb = blockIdx.y, lt64 = blockIdx.x;
    const int lt = lt64 >> 1, half = lt64 & 1;

    const uint32_t* Aglob = g_W2h + ((size_t)(e * 2 + cb) * 32) * CH;
    const uint32_t* Bglob = g_Hth + ((size_t)(p * 8 + lt) * 32) * CH;

    const int warpM = warp >> 1, warpN = warp & 1;  // 4x2: warp tile 32(c) x 32(l)

    auto load_chunk = [&](int kc, int buf) {
        const uint32_t sd = sm_u + (uint32_t)(buf * STAGE_U32) * 4;
        const uint32_t* as = Aglob + (size_t)kc * CH;
        #pragma unroll
        for (int it = 0; it < 2; it++) {
            const int i4 = tid + it * 256;
            cp16(sd + (uint32_t)i4 * 16, as + (size_t)i4 * 4);
        }
        const int k0 = tid >> 7, off = (tid & 127) * 4;
        const uint32_t* bs = Bglob + (size_t)kc * CH + (k0 * 16 + half * 8) * 64;
        cp16(sd + (uint32_t)(CH + k0 * 512 + off) * 4, bs + off);
    };

    float acc[2][4][4];
    #pragma unroll
    for (int mi = 0; mi < 2; mi++)
        #pragma unroll
        for (int ni = 0; ni < 4; ni++)
            #pragma unroll
            for (int r = 0; r < 4; r++) acc[mi][ni][r] = 0.f;

    load_chunk(0, 0); cp_commit();
    load_chunk(1, 1); cp_commit();
    load_chunk(2, 2); cp_commit();

    for (int kc = 0; kc < 32; kc++) {
        cp_wait<2>();
        __syncthreads();
        if (kc + 3 < 32) load_chunk(kc + 3, (kc + 3) & 3);
        cp_commit();

        const uint32_t* Ab = smu + (kc & 3) * STAGE_U32;
        const uint32_t* Bb = Ab + CH;
        #pragma unroll
        for (int k0 = 0; k0 < 2; k0++) {
            uint4 av[2];
            #pragma unroll
            for (int mi = 0; mi < 2; mi++)
                av[mi] = *(const uint4*)(Ab + ((k0 * 8 + warpM * 2 + mi) * 32 + lane) * 4);
            uint2 bv[4];
            #pragma unroll
            for (int ni = 0; ni < 4; ni++)
                bv[ni] = *(const uint2*)(Bb + ((k0 * 8 + warpN * 4 + ni) * 32 + lane) * 2);
            #pragma unroll
            for (int ni = 0; ni < 4; ni++)
                #pragma unroll
                for (int mi = 0; mi < 2; mi++)
                    mma_f16(acc[mi][ni], (const unsigned*)&av[mi], bv[ni].x, bv[ni].y);
        }
    }

    // epilogue: + b2 -> y, direct float2 stores (sector-complete per tg group)
    #pragma unroll
    for (int mi = 0; mi < 2; mi++) {
        #pragma unroll
        for (int r2 = 0; r2 < 2; r2++) {
            const int c = cb * 128 + (warpM * 2 + mi) * 16 + g + r2 * 8;
            const float bias = __ldg(b2 + e * C_ + c);
            float* yp = y + ((size_t)p * C_ + c) * L_ + lt64 * 64;
            #pragma unroll
            for (int ni = 0; ni < 4; ni++) {
                const int l = warpN * 32 + ni * 8 + tg * 2;
                float2 v;
                v.x = acc[mi][ni][r2 * 2 + 0] + bias;
                v.y = acc[mi][ni][r2 * 2 + 1] + bias;
                *(float2*)(yp + l) = v;
            }
        }
    }
}

extern "C" void kernel_launch(void* const* d_in, const int* in_sizes, int n_in,
                              void* d_out, int out_size) {
    const float* x  = (const float*)d_in[0];
    const float* W1 = (const float*)d_in[1];
    const float* b1 = (const float*)d_in[2];
    const float* W2 = (const float*)d_in[3];
    const float* b2 = (const float*)d_in[4];
    float* y = (float*)d_out;

    cudaFuncSetAttribute(experts_k1, cudaFuncAttributeMaxDynamicSharedMemorySize, (int)MAIN_SMEM);
    cudaFuncSetAttribute(experts_k2, cudaFuncAttributeMaxDynamicSharedMemorySize, (int)MAIN_SMEM);

    prep_x <<<dim3(8, B_ * E_), 256>>>(x);     // 1024 CTAs
    prep_w1<<<dim3(8, E_), 256>>>(W1);         //  128 CTAs
    prep_w2<<<dim3(2, E_), 256>>>(W2);         //   32 CTAs

    experts_k1<<<dim3(16, 8, B_ * E_), 256, MAIN_SMEM>>>(b1);       // 16384 CTAs
    experts_k2<<<dim3(16, 2, B_ * E_), 256, MAIN_SMEM>>>(b2, y);    //  4096 CTAs
}